// round 8
// baseline (speedup 1.0000x reference)
#include <cuda_runtime.h>
#include <cuda_fp16.h>

#define N_USERS 100000
#define N_ITEMS 50000
#define N_NODES 150000  // N_USERS + N_ITEMS
#define EMBED   64
#define NNZ     4000000
#define BATCH   4096
#define ROW2    32            // EMBED floats = 32 float2
#define TOTAL2  (N_NODES * ROW2)

// ---------------------------------------------------------------------------
// Device-global scratch. Three fp16 layer tables; layer 3 is computed only
// at the 12k batch rows, fused into the final gather (fp32 path).
// ---------------------------------------------------------------------------
__device__ __half g_E0h[N_NODES * EMBED];
__device__ __half g_E1h[N_NODES * EMBED];
__device__ __half g_E2h[N_NODES * EMBED];

__device__ int  g_cnt[N_NODES];    // degree histogram
__device__ int  g_off[N_NODES];    // exclusive offsets
__device__ int  g_rank[NNZ];       // per-edge rank within its row
__device__ int  g_bsum[256];       // per-segment sums (147 used)
__device__ int2 g_edges[NNZ];      // packed (col, a) sorted by row — 32 MB

// ---------------------------------------------------------------------------
// init + hist fused: E0h = fp16(concat(eu, ei));
// rank[e] = cnt[row[e]]++  — 4-edge batches to overlap ATOMG return latency
// ---------------------------------------------------------------------------
__global__ void lgcn_init_hist(const float2* __restrict__ eu,
                               const float2* __restrict__ ei,
                               const int* __restrict__ row) {
    half2* E0h2 = reinterpret_cast<half2*>(g_E0h);
    const int stride = gridDim.x * blockDim.x;
    const int gid = blockIdx.x * blockDim.x + threadIdx.x;
    const int user2 = N_USERS * ROW2;
    for (int i = gid; i < TOTAL2; i += stride) {
        float2 v = (i < user2) ? eu[i] : ei[i - user2];
        E0h2[i] = __float22half2_rn(v);
    }
    // NNZ % 4 == 0: quad-batched histogram
    const int nq = NNZ >> 2;
    for (int q = gid; q < nq; q += stride) {
        const int e = q << 2;
        int r0 = __ldg(row + e + 0);
        int r1 = __ldg(row + e + 1);
        int r2 = __ldg(row + e + 2);
        int r3 = __ldg(row + e + 3);
        int k0 = atomicAdd(&g_cnt[r0], 1);
        int k1 = atomicAdd(&g_cnt[r1], 1);
        int k2 = atomicAdd(&g_cnt[r2], 1);
        int k3 = atomicAdd(&g_cnt[r3], 1);
        g_rank[e + 0] = k0;
        g_rank[e + 1] = k1;
        g_rank[e + 2] = k2;
        g_rank[e + 3] = k3;
    }
}

// ---------------------------------------------------------------------------
// CSR offsets: per-segment scan, then each block derives its own base
// ---------------------------------------------------------------------------
#define SCAN_B 1024
__global__ void k_scan_local() {
    __shared__ int s[SCAN_B];
    const int tid = threadIdx.x;
    const int i = blockIdx.x * SCAN_B + tid;
    int v = (i < N_NODES) ? g_cnt[i] : 0;
    s[tid] = v;
    __syncthreads();
    #pragma unroll
    for (int d = 1; d < SCAN_B; d <<= 1) {
        int t = (tid >= d) ? s[tid - d] : 0;
        __syncthreads();
        s[tid] += t;
        __syncthreads();
    }
    if (i < N_NODES) g_off[i] = s[tid] - v;          // exclusive within segment
    if (tid == SCAN_B - 1) g_bsum[blockIdx.x] = s[tid];
}

__global__ void k_scan_add() {
    __shared__ int base_s;
    const int tid = threadIdx.x;
    if (tid == 0) base_s = 0;
    __syncthreads();
    int partial = 0;
    for (int k = tid; k < blockIdx.x; k += blockDim.x) partial += g_bsum[k];
    #pragma unroll
    for (int d = 16; d; d >>= 1) partial += __shfl_down_sync(0xffffffffu, partial, d);
    if ((tid & 31) == 0 && partial) atomicAdd(&base_s, partial);
    __syncthreads();
    const int i = blockIdx.x * SCAN_B + tid;        // blockDim == SCAN_B
    if (i < N_NODES) g_off[i] += base_s;
}

// ---------------------------------------------------------------------------
// scatter, atomic-free, 4-edge batched: 4 independent random off[r] loads
// in flight per thread iteration (amortizes L2 latency 4-way).
// ---------------------------------------------------------------------------
__global__ void k_scatter(const int* __restrict__ row,
                          const int* __restrict__ col,
                          const float* __restrict__ a) {
    const int stride = gridDim.x * blockDim.x;
    const int nq = NNZ >> 2;
    for (int q = blockIdx.x * blockDim.x + threadIdx.x; q < nq; q += stride) {
        const int e = q << 2;
        int r0 = __ldg(row + e + 0);
        int r1 = __ldg(row + e + 1);
        int r2 = __ldg(row + e + 2);
        int r3 = __ldg(row + e + 3);
        int o0 = __ldg(&g_off[r0]);
        int o1 = __ldg(&g_off[r1]);
        int o2 = __ldg(&g_off[r2]);
        int o3 = __ldg(&g_off[r3]);
        int k0 = __ldg(&g_rank[e + 0]);
        int k1 = __ldg(&g_rank[e + 1]);
        int k2 = __ldg(&g_rank[e + 2]);
        int k3 = __ldg(&g_rank[e + 3]);
        int c0 = __ldg(col + e + 0);
        int c1 = __ldg(col + e + 1);
        int c2 = __ldg(col + e + 2);
        int c3 = __ldg(col + e + 3);
        float a0 = __ldg(a + e + 0);
        float a1 = __ldg(a + e + 1);
        float a2 = __ldg(a + e + 2);
        float a3 = __ldg(a + e + 3);
        g_edges[o0 + k0] = make_int2(c0, __float_as_int(a0));
        g_edges[o1 + k1] = make_int2(c1, __float_as_int(a1));
        g_edges[o2 + k2] = make_int2(c2, __float_as_int(a2));
        g_edges[o3 + k3] = make_int2(c3, __float_as_int(a3));
    }
}

// ---------------------------------------------------------------------------
// CSR SpMM, fp16 in/out, fp32 math. One warp per node, FOUR edges per
// iteration (eg = lane>>3), unroll 4 -> up to 16 edges / 4 gather-LDGs in
// flight per warp. 8 lanes × 16B cover the 128B row.
// ---------------------------------------------------------------------------
#define SPMM_T 256
__global__ void lgcn_csr(const uint4* __restrict__ src,
                         uint4* __restrict__ dst) {
    const int warp = (blockIdx.x * SPMM_T + threadIdx.x) >> 5;
    const int lane = threadIdx.x & 31;
    if (warp >= N_NODES) return;
    const int s  = __ldg(&g_off[warp]);
    const int n  = __ldg(&g_cnt[warp]);
    const int eg = lane >> 3;          // 0..3: which edge of the quad
    const int l8 = lane & 7;           // 16B chunk within the 128B row

    float2 s0 = make_float2(0.f, 0.f), s1 = s0, s2 = s0, s3 = s0;
    #pragma unroll 4
    for (int base = 0; base < n; base += 4) {
        const int idx = base + eg;
        const int2 e = (idx < n) ? __ldg(g_edges + s + idx) : make_int2(0, 0);
        const float av = __int_as_float(e.y);
        uint4 h = __ldg(src + ((size_t)e.x << 3) + l8);
        float2 v0 = __half22float2(*reinterpret_cast<half2*>(&h.x));
        float2 v1 = __half22float2(*reinterpret_cast<half2*>(&h.y));
        float2 v2 = __half22float2(*reinterpret_cast<half2*>(&h.z));
        float2 v3 = __half22float2(*reinterpret_cast<half2*>(&h.w));
        s0.x += av * v0.x; s0.y += av * v0.y;
        s1.x += av * v1.x; s1.y += av * v1.y;
        s2.x += av * v2.x; s2.y += av * v2.y;
        s3.x += av * v3.x; s3.y += av * v3.y;
    }
    // combine the 4 edge-groups (lanes with equal l8)
    #pragma unroll
    for (int d = 8; d <= 16; d <<= 1) {
        s0.x += __shfl_xor_sync(0xffffffffu, s0.x, d);
        s0.y += __shfl_xor_sync(0xffffffffu, s0.y, d);
        s1.x += __shfl_xor_sync(0xffffffffu, s1.x, d);
        s1.y += __shfl_xor_sync(0xffffffffu, s1.y, d);
        s2.x += __shfl_xor_sync(0xffffffffu, s2.x, d);
        s2.y += __shfl_xor_sync(0xffffffffu, s2.y, d);
        s3.x += __shfl_xor_sync(0xffffffffu, s3.x, d);
        s3.y += __shfl_xor_sync(0xffffffffu, s3.y, d);
    }
    if (eg == 0) {
        half2 p0 = __floats2half2_rn(s0.x, s0.y);
        half2 p1 = __floats2half2_rn(s1.x, s1.y);
        half2 p2 = __floats2half2_rn(s2.x, s2.y);
        half2 p3 = __floats2half2_rn(s3.x, s3.y);
        uint4 o;
        o.x = *reinterpret_cast<unsigned*>(&p0);
        o.y = *reinterpret_cast<unsigned*>(&p1);
        o.z = *reinterpret_cast<unsigned*>(&p2);
        o.w = *reinterpret_cast<unsigned*>(&p3);
        dst[((size_t)warp << 3) + l8] = o;
    }
}

// ---------------------------------------------------------------------------
// Fused layer-3 + gather: one warp per output row.
//   e3 = sum_j a[j] * E2[col[j]]          (fp32, never quantized)
//   out[r] = 0.25 * ((E0+E1+E2)[node] + e3)
// ---------------------------------------------------------------------------
__global__ void lgcn_last(const int* __restrict__ bu,
                          const int* __restrict__ bp,
                          const int* __restrict__ bn,
                          float4* __restrict__ out) {
    const int warp = (blockIdx.x * blockDim.x + threadIdx.x) >> 5;
    const int lane = threadIdx.x & 31;
    if (warp >= 3 * BATCH) return;
    const int which = warp / BATCH;
    const int b     = warp - which * BATCH;
    int node;
    if (which == 0)      node = __ldg(bu + b);
    else if (which == 1) node = N_USERS + __ldg(bp + b);
    else                 node = N_USERS + __ldg(bn + b);

    const int s  = __ldg(&g_off[node]);
    const int n  = __ldg(&g_cnt[node]);
    const int eg = lane >> 3;
    const int l8 = lane & 7;

    const uint4* E2 = reinterpret_cast<const uint4*>(g_E2h);
    float2 s0 = make_float2(0.f, 0.f), s1 = s0, s2 = s0, s3 = s0;
    #pragma unroll 4
    for (int base = 0; base < n; base += 4) {
        const int idx = base + eg;
        const int2 e = (idx < n) ? __ldg(g_edges + s + idx) : make_int2(0, 0);
        const float av = __int_as_float(e.y);
        uint4 h = __ldg(E2 + ((size_t)e.x << 3) + l8);
        float2 v0 = __half22float2(*reinterpret_cast<half2*>(&h.x));
        float2 v1 = __half22float2(*reinterpret_cast<half2*>(&h.y));
        float2 v2 = __half22float2(*reinterpret_cast<half2*>(&h.z));
        float2 v3 = __half22float2(*reinterpret_cast<half2*>(&h.w));
        s0.x += av * v0.x; s0.y += av * v0.y;
        s1.x += av * v1.x; s1.y += av * v1.y;
        s2.x += av * v2.x; s2.y += av * v2.y;
        s3.x += av * v3.x; s3.y += av * v3.y;
    }
    #pragma unroll
    for (int d = 8; d <= 16; d <<= 1) {
        s0.x += __shfl_xor_sync(0xffffffffu, s0.x, d);
        s0.y += __shfl_xor_sync(0xffffffffu, s0.y, d);
        s1.x += __shfl_xor_sync(0xffffffffu, s1.x, d);
        s1.y += __shfl_xor_sync(0xffffffffu, s1.y, d);
        s2.x += __shfl_xor_sync(0xffffffffu, s2.x, d);
        s2.y += __shfl_xor_sync(0xffffffffu, s2.y, d);
        s3.x += __shfl_xor_sync(0xffffffffu, s3.x, d);
        s3.y += __shfl_xor_sync(0xffffffffu, s3.y, d);
    }
    if (eg == 0) {
        // add E0+E1+E2 at node, scale, write fp32
        const size_t o = ((size_t)node << 3) + l8;
        const uint4* tabs[3] = {
            reinterpret_cast<const uint4*>(g_E0h),
            reinterpret_cast<const uint4*>(g_E1h),
            reinterpret_cast<const uint4*>(g_E2h)
        };
        #pragma unroll
        for (int t = 0; t < 3; t++) {
            uint4 h = __ldg(tabs[t] + o);
            float2 v0 = __half22float2(*reinterpret_cast<half2*>(&h.x));
            float2 v1 = __half22float2(*reinterpret_cast<half2*>(&h.y));
            float2 v2 = __half22float2(*reinterpret_cast<half2*>(&h.z));
            float2 v3 = __half22float2(*reinterpret_cast<half2*>(&h.w));
            s0.x += v0.x; s0.y += v0.y;
            s1.x += v1.x; s1.y += v1.y;
            s2.x += v2.x; s2.y += v2.y;
            s3.x += v3.x; s3.y += v3.y;
        }
        const float sc = 0.25f;   // 1/(N_LAYERS+1)
        float4* orow = out + ((size_t)warp << 4) + l8 * 2;
        orow[0] = make_float4(s0.x * sc, s0.y * sc, s1.x * sc, s1.y * sc);
        orow[1] = make_float4(s2.x * sc, s2.y * sc, s3.x * sc, s3.y * sc);
    }
}

// ---------------------------------------------------------------------------
// launch
// ---------------------------------------------------------------------------
extern "C" void kernel_launch(void* const* d_in, const int* in_sizes, int n_in,
                              void* d_out, int out_size) {
    const int*   batch_user = (const int*)  d_in[0];
    const int*   batch_pos  = (const int*)  d_in[1];
    const int*   batch_neg  = (const int*)  d_in[2];
    const float* embed_user = (const float*)d_in[3];
    const float* embed_item = (const float*)d_in[4];
    const int*   row_idx    = (const int*)  d_in[5];
    const int*   col_idx    = (const int*)  d_in[6];
    const float* a_vals     = (const float*)d_in[7];
    float* out = (float*)d_out;

    uint4 *E0, *E1, *E2;
    void* cntp = nullptr;
    cudaGetSymbolAddress((void**)&E0, g_E0h);
    cudaGetSymbolAddress((void**)&E1, g_E1h);
    cudaGetSymbolAddress((void**)&E2, g_E2h);
    cudaGetSymbolAddress(&cntp, g_cnt);

    const int T = 256;
    const int initBlocks = 2048;
    const int edgeBlocks = 148 * 8;
    const int scanBlocks = (N_NODES + SCAN_B - 1) / SCAN_B;     // 147
    const int csrBlocks  = (N_NODES * 32 + SPMM_T - 1) / SPMM_T;
    const int lastBlocks = (3 * BATCH * 32 + T - 1) / T;

    cudaMemsetAsync(cntp, 0, N_NODES * sizeof(int));
    lgcn_init_hist<<<initBlocks, T>>>((const float2*)embed_user,
                                      (const float2*)embed_item, row_idx);

    k_scan_local<<<scanBlocks, SCAN_B>>>();
    k_scan_add<<<scanBlocks, SCAN_B>>>();
    k_scatter<<<edgeBlocks, T>>>(row_idx, col_idx, a_vals);

    // layers 1 and 2 over all nodes
    lgcn_csr<<<csrBlocks, SPMM_T>>>(E0, E1);
    lgcn_csr<<<csrBlocks, SPMM_T>>>(E1, E2);

    // fused layer 3 + accumulate + gather over the 12k batch rows only
    lgcn_last<<<lastBlocks, T>>>(batch_user, batch_pos, batch_neg,
                                 (float4*)out);
}

// round 9
// speedup vs baseline: 1.4318x; 1.4318x over previous
#include <cuda_runtime.h>
#include <cuda_fp16.h>

#define N_USERS 100000
#define N_ITEMS 50000
#define N_NODES 150000  // N_USERS + N_ITEMS
#define EMBED   64
#define NNZ     4000000
#define BATCH   4096
#define ROW2    32            // EMBED floats = 32 float2
#define TOTAL2  (N_NODES * ROW2)

// ---------------------------------------------------------------------------
// Device-global scratch. Three fp16 layer tables; layer 3 is computed only
// at the 12k batch rows, fused into the final gather (fp32 path).
// ---------------------------------------------------------------------------
__device__ __half g_E0h[N_NODES * EMBED];
__device__ __half g_E1h[N_NODES * EMBED];
__device__ __half g_E2h[N_NODES * EMBED];

__device__ int  g_cnt[N_NODES];    // degree histogram
__device__ int  g_off[N_NODES];    // exclusive offsets
__device__ int  g_rank[NNZ];       // per-edge rank within its row
__device__ int  g_bsum[256];       // per-segment sums (147 used)
__device__ int2 g_edges[NNZ];      // packed (col, a) sorted by row — 32 MB

// ---------------------------------------------------------------------------
// init + hist fused: E0h = fp16(concat(eu, ei));
// rank[e] = cnt[row[e]]++  — int4-vectorized row loads (coalesced), 4
// independent ATOMG returns in flight per thread.
// ---------------------------------------------------------------------------
__global__ void lgcn_init_hist(const float2* __restrict__ eu,
                               const float2* __restrict__ ei,
                               const int* __restrict__ row) {
    half2* E0h2 = reinterpret_cast<half2*>(g_E0h);
    const int stride = gridDim.x * blockDim.x;
    const int gid = blockIdx.x * blockDim.x + threadIdx.x;
    const int user2 = N_USERS * ROW2;
    for (int i = gid; i < TOTAL2; i += stride) {
        float2 v = (i < user2) ? eu[i] : ei[i - user2];
        E0h2[i] = __float22half2_rn(v);
    }
    // NNZ % 4 == 0: vector-batched histogram
    const int4* row4 = reinterpret_cast<const int4*>(row);
    int4* rank4 = reinterpret_cast<int4*>(g_rank);
    const int nq = NNZ >> 2;
    for (int q = gid; q < nq; q += stride) {
        int4 r = __ldg(row4 + q);
        int4 k;
        k.x = atomicAdd(&g_cnt[r.x], 1);
        k.y = atomicAdd(&g_cnt[r.y], 1);
        k.z = atomicAdd(&g_cnt[r.z], 1);
        k.w = atomicAdd(&g_cnt[r.w], 1);
        rank4[q] = k;
    }
}

// ---------------------------------------------------------------------------
// CSR offsets: per-segment scan, then each block derives its own base
// ---------------------------------------------------------------------------
#define SCAN_B 1024
__global__ void k_scan_local() {
    __shared__ int s[SCAN_B];
    const int tid = threadIdx.x;
    const int i = blockIdx.x * SCAN_B + tid;
    int v = (i < N_NODES) ? g_cnt[i] : 0;
    s[tid] = v;
    __syncthreads();
    #pragma unroll
    for (int d = 1; d < SCAN_B; d <<= 1) {
        int t = (tid >= d) ? s[tid - d] : 0;
        __syncthreads();
        s[tid] += t;
        __syncthreads();
    }
    if (i < N_NODES) g_off[i] = s[tid] - v;          // exclusive within segment
    if (tid == SCAN_B - 1) g_bsum[blockIdx.x] = s[tid];
}

__global__ void k_scan_add() {
    __shared__ int base_s;
    const int tid = threadIdx.x;
    if (tid == 0) base_s = 0;
    __syncthreads();
    int partial = 0;
    for (int k = tid; k < blockIdx.x; k += blockDim.x) partial += g_bsum[k];
    #pragma unroll
    for (int d = 16; d; d >>= 1) partial += __shfl_down_sync(0xffffffffu, partial, d);
    if ((tid & 31) == 0 && partial) atomicAdd(&base_s, partial);
    __syncthreads();
    const int i = blockIdx.x * SCAN_B + tid;        // blockDim == SCAN_B
    if (i < N_NODES) g_off[i] += base_s;
}

// ---------------------------------------------------------------------------
// scatter, atomic-free, int4-vectorized: streaming loads stay fully
// coalesced (one 16B LDG per array per quad); the 4 random off[r] loads
// are independent -> MLP 4 on the latency chain.
// ---------------------------------------------------------------------------
__global__ void k_scatter(const int* __restrict__ row,
                          const int* __restrict__ col,
                          const float* __restrict__ a) {
    const int4*   row4  = reinterpret_cast<const int4*>(row);
    const int4*   col4  = reinterpret_cast<const int4*>(col);
    const float4* a4    = reinterpret_cast<const float4*>(a);
    const int4*   rank4 = reinterpret_cast<const int4*>(g_rank);
    const int stride = gridDim.x * blockDim.x;
    const int nq = NNZ >> 2;
    for (int q = blockIdx.x * blockDim.x + threadIdx.x; q < nq; q += stride) {
        int4   r = __ldg(row4 + q);
        int4   k = __ldg(rank4 + q);
        int4   c = __ldg(col4 + q);
        float4 w = __ldg(a4 + q);
        int o0 = __ldg(&g_off[r.x]);
        int o1 = __ldg(&g_off[r.y]);
        int o2 = __ldg(&g_off[r.z]);
        int o3 = __ldg(&g_off[r.w]);
        g_edges[o0 + k.x] = make_int2(c.x, __float_as_int(w.x));
        g_edges[o1 + k.y] = make_int2(c.y, __float_as_int(w.y));
        g_edges[o2 + k.z] = make_int2(c.z, __float_as_int(w.z));
        g_edges[o3 + k.w] = make_int2(c.w, __float_as_int(w.w));
    }
}

// ---------------------------------------------------------------------------
// CSR SpMM, fp16 in/out, fp32 math. One warp per node, FOUR edges per
// iteration: edge-group g = lane>>3 handles edge base+g; 8 lanes × 16B
// (uint4 = 8 halves) cover the 128B row. (R7 configuration, unroll 2.)
// ---------------------------------------------------------------------------
#define SPMM_T 256
__global__ void lgcn_csr(const uint4* __restrict__ src,
                         uint4* __restrict__ dst) {
    const int warp = (blockIdx.x * SPMM_T + threadIdx.x) >> 5;
    const int lane = threadIdx.x & 31;
    if (warp >= N_NODES) return;
    const int s  = __ldg(&g_off[warp]);
    const int n  = __ldg(&g_cnt[warp]);
    const int eg = lane >> 3;          // 0..3: which edge of the quad
    const int l8 = lane & 7;           // 16B chunk within the 128B row

    float2 s0 = make_float2(0.f, 0.f), s1 = s0, s2 = s0, s3 = s0;
    #pragma unroll 2
    for (int base = 0; base < n; base += 4) {
        const int idx = base + eg;
        const int2 e = (idx < n) ? __ldg(g_edges + s + idx) : make_int2(0, 0);
        const float av = __int_as_float(e.y);
        uint4 h = __ldg(src + ((size_t)e.x << 3) + l8);
        float2 v0 = __half22float2(*reinterpret_cast<half2*>(&h.x));
        float2 v1 = __half22float2(*reinterpret_cast<half2*>(&h.y));
        float2 v2 = __half22float2(*reinterpret_cast<half2*>(&h.z));
        float2 v3 = __half22float2(*reinterpret_cast<half2*>(&h.w));
        s0.x += av * v0.x; s0.y += av * v0.y;
        s1.x += av * v1.x; s1.y += av * v1.y;
        s2.x += av * v2.x; s2.y += av * v2.y;
        s3.x += av * v3.x; s3.y += av * v3.y;
    }
    // combine the 4 edge-groups (lanes with equal l8)
    #pragma unroll
    for (int d = 8; d <= 16; d <<= 1) {
        s0.x += __shfl_xor_sync(0xffffffffu, s0.x, d);
        s0.y += __shfl_xor_sync(0xffffffffu, s0.y, d);
        s1.x += __shfl_xor_sync(0xffffffffu, s1.x, d);
        s1.y += __shfl_xor_sync(0xffffffffu, s1.y, d);
        s2.x += __shfl_xor_sync(0xffffffffu, s2.x, d);
        s2.y += __shfl_xor_sync(0xffffffffu, s2.y, d);
        s3.x += __shfl_xor_sync(0xffffffffu, s3.x, d);
        s3.y += __shfl_xor_sync(0xffffffffu, s3.y, d);
    }
    if (eg == 0) {
        half2 p0 = __floats2half2_rn(s0.x, s0.y);
        half2 p1 = __floats2half2_rn(s1.x, s1.y);
        half2 p2 = __floats2half2_rn(s2.x, s2.y);
        half2 p3 = __floats2half2_rn(s3.x, s3.y);
        uint4 o;
        o.x = *reinterpret_cast<unsigned*>(&p0);
        o.y = *reinterpret_cast<unsigned*>(&p1);
        o.z = *reinterpret_cast<unsigned*>(&p2);
        o.w = *reinterpret_cast<unsigned*>(&p3);
        dst[((size_t)warp << 3) + l8] = o;
    }
}

// ---------------------------------------------------------------------------
// Fused layer-3 + gather: one warp per output row.
//   e3 = sum_j a[j] * E2[col[j]]          (fp32, never quantized)
//   out[r] = 0.25 * ((E0+E1+E2)[node] + e3)
// ---------------------------------------------------------------------------
__global__ void lgcn_last(const int* __restrict__ bu,
                          const int* __restrict__ bp,
                          const int* __restrict__ bn,
                          float4* __restrict__ out) {
    const int warp = (blockIdx.x * blockDim.x + threadIdx.x) >> 5;
    const int lane = threadIdx.x & 31;
    if (warp >= 3 * BATCH) return;
    const int which = warp / BATCH;
    const int b     = warp - which * BATCH;
    int node;
    if (which == 0)      node = __ldg(bu + b);
    else if (which == 1) node = N_USERS + __ldg(bp + b);
    else                 node = N_USERS + __ldg(bn + b);

    const int s  = __ldg(&g_off[node]);
    const int n  = __ldg(&g_cnt[node]);
    const int eg = lane >> 3;
    const int l8 = lane & 7;

    const uint4* E2 = reinterpret_cast<const uint4*>(g_E2h);
    float2 s0 = make_float2(0.f, 0.f), s1 = s0, s2 = s0, s3 = s0;
    for (int base = 0; base < n; base += 4) {
        const int idx = base + eg;
        const int2 e = (idx < n) ? __ldg(g_edges + s + idx) : make_int2(0, 0);
        const float av = __int_as_float(e.y);
        uint4 h = __ldg(E2 + ((size_t)e.x << 3) + l8);
        float2 v0 = __half22float2(*reinterpret_cast<half2*>(&h.x));
        float2 v1 = __half22float2(*reinterpret_cast<half2*>(&h.y));
        float2 v2 = __half22float2(*reinterpret_cast<half2*>(&h.z));
        float2 v3 = __half22float2(*reinterpret_cast<half2*>(&h.w));
        s0.x += av * v0.x; s0.y += av * v0.y;
        s1.x += av * v1.x; s1.y += av * v1.y;
        s2.x += av * v2.x; s2.y += av * v2.y;
        s3.x += av * v3.x; s3.y += av * v3.y;
    }
    #pragma unroll
    for (int d = 8; d <= 16; d <<= 1) {
        s0.x += __shfl_xor_sync(0xffffffffu, s0.x, d);
        s0.y += __shfl_xor_sync(0xffffffffu, s0.y, d);
        s1.x += __shfl_xor_sync(0xffffffffu, s1.x, d);
        s1.y += __shfl_xor_sync(0xffffffffu, s1.y, d);
        s2.x += __shfl_xor_sync(0xffffffffu, s2.x, d);
        s2.y += __shfl_xor_sync(0xffffffffu, s2.y, d);
        s3.x += __shfl_xor_sync(0xffffffffu, s3.x, d);
        s3.y += __shfl_xor_sync(0xffffffffu, s3.y, d);
    }
    if (eg == 0) {
        // add E0+E1+E2 at node, scale, write fp32
        const size_t o = ((size_t)node << 3) + l8;
        const uint4* tabs[3] = {
            reinterpret_cast<const uint4*>(g_E0h),
            reinterpret_cast<const uint4*>(g_E1h),
            reinterpret_cast<const uint4*>(g_E2h)
        };
        #pragma unroll
        for (int t = 0; t < 3; t++) {
            uint4 h = __ldg(tabs[t] + o);
            float2 v0 = __half22float2(*reinterpret_cast<half2*>(&h.x));
            float2 v1 = __half22float2(*reinterpret_cast<half2*>(&h.y));
            float2 v2 = __half22float2(*reinterpret_cast<half2*>(&h.z));
            float2 v3 = __half22float2(*reinterpret_cast<half2*>(&h.w));
            s0.x += v0.x; s0.y += v0.y;
            s1.x += v1.x; s1.y += v1.y;
            s2.x += v2.x; s2.y += v2.y;
            s3.x += v3.x; s3.y += v3.y;
        }
        const float sc = 0.25f;   // 1/(N_LAYERS+1)
        float4* orow = out + ((size_t)warp << 4) + l8 * 2;
        orow[0] = make_float4(s0.x * sc, s0.y * sc, s1.x * sc, s1.y * sc);
        orow[1] = make_float4(s2.x * sc, s2.y * sc, s3.x * sc, s3.y * sc);
    }
}

// ---------------------------------------------------------------------------
// launch
// ---------------------------------------------------------------------------
extern "C" void kernel_launch(void* const* d_in, const int* in_sizes, int n_in,
                              void* d_out, int out_size) {
    const int*   batch_user = (const int*)  d_in[0];
    const int*   batch_pos  = (const int*)  d_in[1];
    const int*   batch_neg  = (const int*)  d_in[2];
    const float* embed_user = (const float*)d_in[3];
    const float* embed_item = (const float*)d_in[4];
    const int*   row_idx    = (const int*)  d_in[5];
    const int*   col_idx    = (const int*)  d_in[6];
    const float* a_vals     = (const float*)d_in[7];
    float* out = (float*)d_out;

    uint4 *E0, *E1, *E2;
    void* cntp = nullptr;
    cudaGetSymbolAddress((void**)&E0, g_E0h);
    cudaGetSymbolAddress((void**)&E1, g_E1h);
    cudaGetSymbolAddress((void**)&E2, g_E2h);
    cudaGetSymbolAddress(&cntp, g_cnt);

    const int T = 256;
    const int initBlocks = 2048;
    const int edgeBlocks = 148 * 8;
    const int scanBlocks = (N_NODES + SCAN_B - 1) / SCAN_B;     // 147
    const int csrBlocks  = (N_NODES * 32 + SPMM_T - 1) / SPMM_T;
    const int lastBlocks = (3 * BATCH * 32 + T - 1) / T;

    cudaMemsetAsync(cntp, 0, N_NODES * sizeof(int));
    lgcn_init_hist<<<initBlocks, T>>>((const float2*)embed_user,
                                      (const float2*)embed_item, row_idx);

    k_scan_local<<<scanBlocks, SCAN_B>>>();
    k_scan_add<<<scanBlocks, SCAN_B>>>();
    k_scatter<<<edgeBlocks, T>>>(row_idx, col_idx, a_vals);

    // layers 1 and 2 over all nodes
    lgcn_csr<<<csrBlocks, SPMM_T>>>(E0, E1);
    lgcn_csr<<<csrBlocks, SPMM_T>>>(E1, E2);

    // fused layer 3 + accumulate + gather over the 12k batch rows only
    lgcn_last<<<lastBlocks, T>>>(batch_user, batch_pos, batch_neg,
                                 (float4*)out);
}

// round 10
// speedup vs baseline: 1.4931x; 1.0429x over previous
#include <cuda_runtime.h>
#include <cuda_fp16.h>

#define N_USERS 100000
#define N_ITEMS 50000
#define N_NODES 150000  // N_USERS + N_ITEMS
#define EMBED   64
#define NNZ     4000000
#define BATCH   4096
#define ROW2    32            // EMBED floats = 32 float2
#define TOTAL2  (N_NODES * ROW2)

// ---------------------------------------------------------------------------
// Device-global scratch. Three fp16 layer tables; layer 3 is computed only
// at the 12k batch rows, fused into the final gather (fp32 path).
// ---------------------------------------------------------------------------
__device__ __half g_E0h[N_NODES * EMBED];
__device__ __half g_E1h[N_NODES * EMBED];
__device__ __half g_E2h[N_NODES * EMBED];

__device__ int  g_cnt[N_NODES];    // degree histogram
__device__ int  g_off[N_NODES];    // exclusive offsets
__device__ int  g_rank[NNZ];       // per-edge rank within its row
__device__ int  g_bsum[256];       // per-segment sums (147 used)
__device__ int2 g_edges[NNZ];      // packed (col, a) sorted by row — 32 MB

// ---------------------------------------------------------------------------
// init + hist fused: E0h = fp16(concat(eu, ei));
// rank[e] = cnt[row[e]]++  — int4-vectorized row loads, 4 ATOMG in flight.
// ---------------------------------------------------------------------------
__global__ void lgcn_init_hist(const float2* __restrict__ eu,
                               const float2* __restrict__ ei,
                               const int* __restrict__ row) {
    half2* E0h2 = reinterpret_cast<half2*>(g_E0h);
    const int stride = gridDim.x * blockDim.x;
    const int gid = blockIdx.x * blockDim.x + threadIdx.x;
    const int user2 = N_USERS * ROW2;
    for (int i = gid; i < TOTAL2; i += stride) {
        float2 v = (i < user2) ? eu[i] : ei[i - user2];
        E0h2[i] = __float22half2_rn(v);
    }
    const int4* row4 = reinterpret_cast<const int4*>(row);
    int4* rank4 = reinterpret_cast<int4*>(g_rank);
    const int nq = NNZ >> 2;
    for (int q = gid; q < nq; q += stride) {
        int4 r = __ldg(row4 + q);
        int4 k;
        k.x = atomicAdd(&g_cnt[r.x], 1);
        k.y = atomicAdd(&g_cnt[r.y], 1);
        k.z = atomicAdd(&g_cnt[r.z], 1);
        k.w = atomicAdd(&g_cnt[r.w], 1);
        rank4[q] = k;
    }
}

// ---------------------------------------------------------------------------
// CSR offsets: per-segment scan, then each block derives its own base
// ---------------------------------------------------------------------------
#define SCAN_B 1024
__global__ void k_scan_local() {
    __shared__ int s[SCAN_B];
    const int tid = threadIdx.x;
    const int i = blockIdx.x * SCAN_B + tid;
    int v = (i < N_NODES) ? g_cnt[i] : 0;
    s[tid] = v;
    __syncthreads();
    #pragma unroll
    for (int d = 1; d < SCAN_B; d <<= 1) {
        int t = (tid >= d) ? s[tid - d] : 0;
        __syncthreads();
        s[tid] += t;
        __syncthreads();
    }
    if (i < N_NODES) g_off[i] = s[tid] - v;          // exclusive within segment
    if (tid == SCAN_B - 1) g_bsum[blockIdx.x] = s[tid];
}

__global__ void k_scan_add() {
    __shared__ int base_s;
    const int tid = threadIdx.x;
    if (tid == 0) base_s = 0;
    __syncthreads();
    int partial = 0;
    for (int k = tid; k < blockIdx.x; k += blockDim.x) partial += g_bsum[k];
    #pragma unroll
    for (int d = 16; d; d >>= 1) partial += __shfl_down_sync(0xffffffffu, partial, d);
    if ((tid & 31) == 0 && partial) atomicAdd(&base_s, partial);
    __syncthreads();
    const int i = blockIdx.x * SCAN_B + tid;        // blockDim == SCAN_B
    if (i < N_NODES) g_off[i] += base_s;
}

// ---------------------------------------------------------------------------
// scatter, atomic-free, int4-vectorized (store-path bound; left as-is)
// ---------------------------------------------------------------------------
__global__ void k_scatter(const int* __restrict__ row,
                          const int* __restrict__ col,
                          const float* __restrict__ a) {
    const int4*   row4  = reinterpret_cast<const int4*>(row);
    const int4*   col4  = reinterpret_cast<const int4*>(col);
    const float4* a4    = reinterpret_cast<const float4*>(a);
    const int4*   rank4 = reinterpret_cast<const int4*>(g_rank);
    const int stride = gridDim.x * blockDim.x;
    const int nq = NNZ >> 2;
    for (int q = blockIdx.x * blockDim.x + threadIdx.x; q < nq; q += stride) {
        int4   r = __ldg(row4 + q);
        int4   k = __ldg(rank4 + q);
        int4   c = __ldg(col4 + q);
        float4 w = __ldg(a4 + q);
        int o0 = __ldg(&g_off[r.x]);
        int o1 = __ldg(&g_off[r.y]);
        int o2 = __ldg(&g_off[r.z]);
        int o3 = __ldg(&g_off[r.w]);
        g_edges[o0 + k.x] = make_int2(c.x, __float_as_int(w.x));
        g_edges[o1 + k.y] = make_int2(c.y, __float_as_int(w.y));
        g_edges[o2 + k.z] = make_int2(c.z, __float_as_int(w.z));
        g_edges[o3 + k.w] = make_int2(c.w, __float_as_int(w.w));
    }
}

// ---------------------------------------------------------------------------
// CSR SpMM, fp16 in/out, fp32 math, SOFTWARE-PIPELINED.
// One warp per node; edge-group eg = lane>>3 handles edge base+eg; 8 lanes
// × 16B cover the 128B row. The next edge quad is prefetched while the
// current quad's gather is in flight, so the edge-load latency is hidden:
// steady-state critical path = one gather, not edge-load + gather.
// ---------------------------------------------------------------------------
#define SPMM_T 256
__global__ void lgcn_csr(const uint4* __restrict__ src,
                         uint4* __restrict__ dst) {
    const int warp = (blockIdx.x * SPMM_T + threadIdx.x) >> 5;
    const int lane = threadIdx.x & 31;
    if (warp >= N_NODES) return;
    const int s  = __ldg(&g_off[warp]);
    const int n  = __ldg(&g_cnt[warp]);
    const int eg = lane >> 3;          // 0..3: which edge of the quad
    const int l8 = lane & 7;           // 16B chunk within the 128B row

    float2 s0 = make_float2(0.f, 0.f), s1 = s0, s2 = s0, s3 = s0;
    int2 e_cur = (eg < n) ? __ldg(g_edges + s + eg) : make_int2(0, 0);
    #pragma unroll 2
    for (int base = 0; base < n; base += 4) {
        // prefetch next quad's edge (independent of this iteration's math)
        const int nidx = base + 4 + eg;
        int2 e_next = (nidx < n) ? __ldg(g_edges + s + nidx) : make_int2(0, 0);
        const float av = __int_as_float(e_cur.y);
        uint4 h = __ldg(src + ((size_t)e_cur.x << 3) + l8);
        float2 v0 = __half22float2(*reinterpret_cast<half2*>(&h.x));
        float2 v1 = __half22float2(*reinterpret_cast<half2*>(&h.y));
        float2 v2 = __half22float2(*reinterpret_cast<half2*>(&h.z));
        float2 v3 = __half22float2(*reinterpret_cast<half2*>(&h.w));
        s0.x += av * v0.x; s0.y += av * v0.y;
        s1.x += av * v1.x; s1.y += av * v1.y;
        s2.x += av * v2.x; s2.y += av * v2.y;
        s3.x += av * v3.x; s3.y += av * v3.y;
        e_cur = e_next;
    }
    // combine the 4 edge-groups (lanes with equal l8)
    #pragma unroll
    for (int d = 8; d <= 16; d <<= 1) {
        s0.x += __shfl_xor_sync(0xffffffffu, s0.x, d);
        s0.y += __shfl_xor_sync(0xffffffffu, s0.y, d);
        s1.x += __shfl_xor_sync(0xffffffffu, s1.x, d);
        s1.y += __shfl_xor_sync(0xffffffffu, s1.y, d);
        s2.x += __shfl_xor_sync(0xffffffffu, s2.x, d);
        s2.y += __shfl_xor_sync(0xffffffffu, s2.y, d);
        s3.x += __shfl_xor_sync(0xffffffffu, s3.x, d);
        s3.y += __shfl_xor_sync(0xffffffffu, s3.y, d);
    }
    if (eg == 0) {
        half2 p0 = __floats2half2_rn(s0.x, s0.y);
        half2 p1 = __floats2half2_rn(s1.x, s1.y);
        half2 p2 = __floats2half2_rn(s2.x, s2.y);
        half2 p3 = __floats2half2_rn(s3.x, s3.y);
        uint4 o;
        o.x = *reinterpret_cast<unsigned*>(&p0);
        o.y = *reinterpret_cast<unsigned*>(&p1);
        o.z = *reinterpret_cast<unsigned*>(&p2);
        o.w = *reinterpret_cast<unsigned*>(&p3);
        dst[((size_t)warp << 3) + l8] = o;
    }
}

// ---------------------------------------------------------------------------
// Fused layer-3 + gather (software-pipelined like lgcn_csr):
//   e3 = sum_j a[j] * E2[col[j]]   (fp32, never quantized)
//   out[r] = 0.25 * ((E0+E1+E2)[node] + e3)
// ---------------------------------------------------------------------------
__global__ void lgcn_last(const int* __restrict__ bu,
                          const int* __restrict__ bp,
                          const int* __restrict__ bn,
                          float4* __restrict__ out) {
    const int warp = (blockIdx.x * blockDim.x + threadIdx.x) >> 5;
    const int lane = threadIdx.x & 31;
    if (warp >= 3 * BATCH) return;
    const int which = warp / BATCH;
    const int b     = warp - which * BATCH;
    int node;
    if (which == 0)      node = __ldg(bu + b);
    else if (which == 1) node = N_USERS + __ldg(bp + b);
    else                 node = N_USERS + __ldg(bn + b);

    const int s  = __ldg(&g_off[node]);
    const int n  = __ldg(&g_cnt[node]);
    const int eg = lane >> 3;
    const int l8 = lane & 7;

    const uint4* E2 = reinterpret_cast<const uint4*>(g_E2h);
    float2 s0 = make_float2(0.f, 0.f), s1 = s0, s2 = s0, s3 = s0;
    int2 e_cur = (eg < n) ? __ldg(g_edges + s + eg) : make_int2(0, 0);
    for (int base = 0; base < n; base += 4) {
        const int nidx = base + 4 + eg;
        int2 e_next = (nidx < n) ? __ldg(g_edges + s + nidx) : make_int2(0, 0);
        const float av = __int_as_float(e_cur.y);
        uint4 h = __ldg(E2 + ((size_t)e_cur.x << 3) + l8);
        float2 v0 = __half22float2(*reinterpret_cast<half2*>(&h.x));
        float2 v1 = __half22float2(*reinterpret_cast<half2*>(&h.y));
        float2 v2 = __half22float2(*reinterpret_cast<half2*>(&h.z));
        float2 v3 = __half22float2(*reinterpret_cast<half2*>(&h.w));
        s0.x += av * v0.x; s0.y += av * v0.y;
        s1.x += av * v1.x; s1.y += av * v1.y;
        s2.x += av * v2.x; s2.y += av * v2.y;
        s3.x += av * v3.x; s3.y += av * v3.y;
        e_cur = e_next;
    }
    #pragma unroll
    for (int d = 8; d <= 16; d <<= 1) {
        s0.x += __shfl_xor_sync(0xffffffffu, s0.x, d);
        s0.y += __shfl_xor_sync(0xffffffffu, s0.y, d);
        s1.x += __shfl_xor_sync(0xffffffffu, s1.x, d);
        s1.y += __shfl_xor_sync(0xffffffffu, s1.y, d);
        s2.x += __shfl_xor_sync(0xffffffffu, s2.x, d);
        s2.y += __shfl_xor_sync(0xffffffffu, s2.y, d);
        s3.x += __shfl_xor_sync(0xffffffffu, s3.x, d);
        s3.y += __shfl_xor_sync(0xffffffffu, s3.y, d);
    }
    if (eg == 0) {
        const size_t o = ((size_t)node << 3) + l8;
        const uint4* tabs[3] = {
            reinterpret_cast<const uint4*>(g_E0h),
            reinterpret_cast<const uint4*>(g_E1h),
            reinterpret_cast<const uint4*>(g_E2h)
        };
        #pragma unroll
        for (int t = 0; t < 3; t++) {
            uint4 h = __ldg(tabs[t] + o);
            float2 v0 = __half22float2(*reinterpret_cast<half2*>(&h.x));
            float2 v1 = __half22float2(*reinterpret_cast<half2*>(&h.y));
            float2 v2 = __half22float2(*reinterpret_cast<half2*>(&h.z));
            float2 v3 = __half22float2(*reinterpret_cast<half2*>(&h.w));
            s0.x += v0.x; s0.y += v0.y;
            s1.x += v1.x; s1.y += v1.y;
            s2.x += v2.x; s2.y += v2.y;
            s3.x += v3.x; s3.y += v3.y;
        }
        const float sc = 0.25f;   // 1/(N_LAYERS+1)
        float4* orow = out + ((size_t)warp << 4) + l8 * 2;
        orow[0] = make_float4(s0.x * sc, s0.y * sc, s1.x * sc, s1.y * sc);
        orow[1] = make_float4(s2.x * sc, s2.y * sc, s3.x * sc, s3.y * sc);
    }
}

// ---------------------------------------------------------------------------
// launch
// ---------------------------------------------------------------------------
extern "C" void kernel_launch(void* const* d_in, const int* in_sizes, int n_in,
                              void* d_out, int out_size) {
    const int*   batch_user = (const int*)  d_in[0];
    const int*   batch_pos  = (const int*)  d_in[1];
    const int*   batch_neg  = (const int*)  d_in[2];
    const float* embed_user = (const float*)d_in[3];
    const float* embed_item = (const float*)d_in[4];
    const int*   row_idx    = (const int*)  d_in[5];
    const int*   col_idx    = (const int*)  d_in[6];
    const float* a_vals     = (const float*)d_in[7];
    float* out = (float*)d_out;

    uint4 *E0, *E1, *E2;
    void* cntp = nullptr;
    cudaGetSymbolAddress((void**)&E0, g_E0h);
    cudaGetSymbolAddress((void**)&E1, g_E1h);
    cudaGetSymbolAddress((void**)&E2, g_E2h);
    cudaGetSymbolAddress(&cntp, g_cnt);

    const int T = 256;
    const int initBlocks = 2048;
    const int edgeBlocks = 148 * 8;
    const int scanBlocks = (N_NODES + SCAN_B - 1) / SCAN_B;     // 147
    const int csrBlocks  = (N_NODES * 32 + SPMM_T - 1) / SPMM_T;
    const int lastBlocks = (3 * BATCH * 32 + T - 1) / T;

    cudaMemsetAsync(cntp, 0, N_NODES * sizeof(int));
    lgcn_init_hist<<<initBlocks, T>>>((const float2*)embed_user,
                                      (const float2*)embed_item, row_idx);

    k_scan_local<<<scanBlocks, SCAN_B>>>();
    k_scan_add<<<scanBlocks, SCAN_B>>>();
    k_scatter<<<edgeBlocks, T>>>(row_idx, col_idx, a_vals);

    // layers 1 and 2 over all nodes
    lgcn_csr<<<csrBlocks, SPMM_T>>>(E0, E1);
    lgcn_csr<<<csrBlocks, SPMM_T>>>(E1, E2);

    // fused layer 3 + accumulate + gather over the 12k batch rows only
    lgcn_last<<<lastBlocks, T>>>(batch_user, batch_pos, batch_neg,
                                 (float4*)out);
}